// round 4
// baseline (speedup 1.0000x reference)
#include <cuda_runtime.h>

#define BATCH_N   32768
#define JDIM      2048
#define ROWS      4
#define THREADS   256

__global__ __launch_bounds__(THREADS)
void qe_kernel(const float* __restrict__ x,
               const float* __restrict__ W,     // [J, 2] row-major
               const float* __restrict__ ph,    // [J, 1]
               float* __restrict__ out)         // [B, 2]
{
    const int row0 = blockIdx.x * ROWS;
    const int tid  = threadIdx.x;

    float acc[ROWS][2];
#pragma unroll
    for (int r = 0; r < ROWS; ++r) { acc[r][0] = 0.f; acc[r][1] = 0.f; }

    const float4* x4 = reinterpret_cast<const float4*>(x + (size_t)row0 * JDIM);

    // Two iterations: lane-contiguous float4 loads (perfect coalescing),
    // jj covers [0,1024) then [1024,2048) across the block.
#pragma unroll
    for (int it = 0; it < JDIM / (THREADS * 4); ++it) {
        const int jj = tid * 4 + it * THREADS * 4;
        const float4 p  = *reinterpret_cast<const float4*>(ph + jj);
        const float4 wa = *reinterpret_cast<const float4*>(W + 2 * jj);      // j=jj,jj+1 : (e0,e1,e0,e1)
        const float4 wb = *reinterpret_cast<const float4*>(W + 2 * jj + 4);  // j=jj+2,jj+3

#pragma unroll
        for (int r = 0; r < ROWS; ++r) {
            const float4 xv = x4[r * (JDIM / 4) + (jj >> 2)];
            const float c0 = __cosf(xv.x * p.x);
            const float c1 = __cosf(xv.y * p.y);
            const float c2 = __cosf(xv.z * p.z);
            const float c3 = __cosf(xv.w * p.w);
            acc[r][0] = fmaf(c0, wa.x, fmaf(c1, wa.z, fmaf(c2, wb.x, fmaf(c3, wb.z, acc[r][0]))));
            acc[r][1] = fmaf(c0, wa.y, fmaf(c1, wa.w, fmaf(c2, wb.y, fmaf(c3, wb.w, acc[r][1]))));
        }
    }

    // Warp-level reduction of all 8 accumulators
#pragma unroll
    for (int r = 0; r < ROWS; ++r)
#pragma unroll
        for (int e = 0; e < 2; ++e)
#pragma unroll
            for (int off = 16; off > 0; off >>= 1)
                acc[r][e] += __shfl_xor_sync(0xFFFFFFFFu, acc[r][e], off);

    __shared__ float s[THREADS / 32][ROWS * 2];
    const int warp = tid >> 5, lane = tid & 31;
    if (lane == 0) {
#pragma unroll
        for (int r = 0; r < ROWS; ++r) {
            s[warp][r * 2 + 0] = acc[r][0];
            s[warp][r * 2 + 1] = acc[r][1];
        }
    }
    __syncthreads();

    if (tid < ROWS * 2) {
        float t = 0.f;
#pragma unroll
        for (int w = 0; w < THREADS / 32; ++w) t += s[w][tid];
        out[(size_t)(row0 + (tid >> 1)) * 2 + (tid & 1)] = t;
    }
}

extern "C" void kernel_launch(void* const* d_in, const int* in_sizes, int n_in,
                              void* d_out, int out_size)
{
    const float* x  = (const float*)d_in[0];   // [32768, 2048] f32
    const float* W  = (const float*)d_in[1];   // [2048, 2]     f32
    const float* ph = (const float*)d_in[2];   // [2048, 1]     f32
    float* out = (float*)d_out;                // [32768, 2]    f32

    qe_kernel<<<BATCH_N / ROWS, THREADS>>>(x, W, ph, out);
}

// round 5
// speedup vs baseline: 1.0149x; 1.0149x over previous
#include <cuda_runtime.h>

#define BATCH_N   32768
#define JDIM      2048
#define ROWS      8
#define THREADS   256
#define NWARP     (THREADS / 32)

__global__ __launch_bounds__(THREADS)
void qe_kernel(const float* __restrict__ x,
               const float* __restrict__ W,     // [J, 2] row-major
               const float* __restrict__ ph,    // [J, 1]
               float* __restrict__ out)         // [B, 2]
{
    const int row0 = blockIdx.x * ROWS;
    const int tid  = threadIdx.x;

    // v[k] = acc for (row r = k>>1, embed e = k&1)
    float v[ROWS * 2];
#pragma unroll
    for (int k = 0; k < ROWS * 2; ++k) v[k] = 0.f;

    const float4* x4 = reinterpret_cast<const float4*>(x + (size_t)row0 * JDIM);

#pragma unroll
    for (int it = 0; it < JDIM / (THREADS * 4); ++it) {
        const int jj = tid * 4 + it * THREADS * 4;
        const float4 p  = *reinterpret_cast<const float4*>(ph + jj);
        const float4 wa = *reinterpret_cast<const float4*>(W + 2 * jj);      // j=jj,jj+1: (e0,e1,e0,e1)
        const float4 wb = *reinterpret_cast<const float4*>(W + 2 * jj + 4);  // j=jj+2,jj+3

#pragma unroll
        for (int r = 0; r < ROWS; ++r) {
            // streaming (evict-first) load: x has zero reuse, keep L2 for W/ph
            const float4 xv = __ldcs(&x4[(size_t)r * (JDIM / 4) + (jj >> 2)]);
            const float c0 = __cosf(xv.x * p.x);
            const float c1 = __cosf(xv.y * p.y);
            const float c2 = __cosf(xv.z * p.z);
            const float c3 = __cosf(xv.w * p.w);
            v[r * 2 + 0] = fmaf(c0, wa.x, fmaf(c1, wa.z, fmaf(c2, wb.x, fmaf(c3, wb.z, v[r * 2 + 0]))));
            v[r * 2 + 1] = fmaf(c0, wa.y, fmaf(c1, wa.w, fmaf(c2, wb.y, fmaf(c3, wb.w, v[r * 2 + 1]))));
        }
    }

    // ---- merged butterfly reduction: 16 accumulators in 31 shuffles ----
    // After each xor-k stage, partner lanes (differing in bit log2(k)) share all
    // selection bits used so far, so select-then-shuffle folds two accumulators
    // into one slot per stage. Final: lane holds full sum of acc index
    // k = b4 | b3<<1 | b2<<2 | b1<<3 (b_i = lane bit i).
    const int lane = tid & 31;
    const int warp = tid >> 5;

#pragma unroll
    for (int i = 0; i < 16; ++i) v[i] += __shfl_xor_sync(0xFFFFFFFFu, v[i], 16);

    float u[8];
    {
        const bool b = lane & 16;
#pragma unroll
        for (int i = 0; i < 8; ++i) u[i] = b ? v[2 * i + 1] : v[2 * i];
#pragma unroll
        for (int i = 0; i < 8; ++i) u[i] += __shfl_xor_sync(0xFFFFFFFFu, u[i], 8);
    }
    float w4[4];
    {
        const bool b = lane & 8;
#pragma unroll
        for (int i = 0; i < 4; ++i) w4[i] = b ? u[2 * i + 1] : u[2 * i];
#pragma unroll
        for (int i = 0; i < 4; ++i) w4[i] += __shfl_xor_sync(0xFFFFFFFFu, w4[i], 4);
    }
    float y[2];
    {
        const bool b = lane & 4;
#pragma unroll
        for (int i = 0; i < 2; ++i) y[i] = b ? w4[2 * i + 1] : w4[2 * i];
#pragma unroll
        for (int i = 0; i < 2; ++i) y[i] += __shfl_xor_sync(0xFFFFFFFFu, y[i], 2);
    }
    float t = (lane & 2) ? y[1] : y[0];
    t += __shfl_xor_sync(0xFFFFFFFFu, t, 1);

    __shared__ float s[NWARP][ROWS * 2];
    if (!(lane & 1)) {
        const int k = ((lane >> 4) & 1) | (((lane >> 3) & 1) << 1)
                    | (((lane >> 2) & 1) << 2) | (((lane >> 1) & 1) << 3);
        s[warp][k] = t;
    }
    __syncthreads();

    if (tid < ROWS * 2) {
        float sum = 0.f;
#pragma unroll
        for (int wi = 0; wi < NWARP; ++wi) sum += s[wi][tid];
        out[(size_t)(row0 + (tid >> 1)) * 2 + (tid & 1)] = sum;
    }
}

extern "C" void kernel_launch(void* const* d_in, const int* in_sizes, int n_in,
                              void* d_out, int out_size)
{
    const float* x  = (const float*)d_in[0];   // [32768, 2048] f32
    const float* W  = (const float*)d_in[1];   // [2048, 2]     f32
    const float* ph = (const float*)d_in[2];   // [2048, 1]     f32
    float* out = (float*)d_out;                // [32768, 2]    f32

    qe_kernel<<<BATCH_N / ROWS, THREADS>>>(x, W, ph, out);
}